// round 14
// baseline (speedup 1.0000x reference)
#include <cuda_runtime.h>
#include <cuda_fp16.h>
#include <math.h>

#define QF_ 0.04508422002777998f   // log2(e)/32

// ------------------------- device scratch (no allocs) ----------------------
__device__ __half g_Xh[(size_t)8192*1024];
__device__ __half g_Wh[(size_t)3072*1024];   // W^T [n][k]
__device__ __half g_Qh[(size_t)64*2048*64];  // [bh][s][d] (pre-scaled by QF)
__device__ __half g_Kh[(size_t)64*2048*64];
__device__ __half g_Vsh[(size_t)64*2048*64]; // [bh][s][d]

// ------------------------------ helpers ------------------------------------
__device__ __forceinline__ unsigned su32(const void* p){
    unsigned a;
    asm("{ .reg .u64 t; cvta.to.shared.u64 t, %1; cvt.u32.u64 %0, t; }":"=r"(a):"l"(p));
    return a;
}
#define SWZ(o) ((unsigned)(o) ^ ((((unsigned)(o)) >> 3) & 0x70))

__device__ __forceinline__ void cpa16(unsigned dst, const void* src){
    asm volatile("cp.async.cg.shared.global [%0], [%1], 16;"::"r"(dst),"l"(src));
}
#define CP_COMMIT() asm volatile("cp.async.commit_group;" ::: "memory")
#define CP_WAIT1()  asm volatile("cp.async.wait_group 1;" ::: "memory")
#define CP_WAIT0()  asm volatile("cp.async.wait_group 0;" ::: "memory")

__device__ __forceinline__ void ldsm4(unsigned* r, unsigned a){
    asm volatile("ldmatrix.sync.aligned.m8n8.x4.shared.b16 {%0,%1,%2,%3}, [%4];"
                 : "=r"(r[0]),"=r"(r[1]),"=r"(r[2]),"=r"(r[3]) : "r"(a));
}
__device__ __forceinline__ void ldsm4t(unsigned* r, unsigned a){
    asm volatile("ldmatrix.sync.aligned.m8n8.x4.trans.shared.b16 {%0,%1,%2,%3}, [%4];"
                 : "=r"(r[0]),"=r"(r[1]),"=r"(r[2]),"=r"(r[3]) : "r"(a));
}
__device__ __forceinline__ void mma16816(float* d, const unsigned* a, unsigned b0, unsigned b1){
    asm volatile("mma.sync.aligned.m16n8k16.row.col.f32.f16.f16.f32 "
                 "{%0,%1,%2,%3},{%4,%5,%6,%7},{%8,%9},{%0,%1,%2,%3};"
                 : "+f"(d[0]),"+f"(d[1]),"+f"(d[2]),"+f"(d[3])
                 : "r"(a[0]),"r"(a[1]),"r"(a[2]),"r"(a[3]),"r"(b0),"r"(b1));
}
__device__ __forceinline__ float ex2f(float x){
    float r; asm("ex2.approx.ftz.f32 %0, %1;":"=f"(r):"f"(x)); return r;
}
__device__ __forceinline__ unsigned packh(float a, float b){
    __half2 h = __floats2half2_rn(a, b);
    return *(unsigned*)&h;
}

// ---------------------------- split X (hi only) ------------------------------
__global__ __launch_bounds__(256) void splitx_kernel(const float* __restrict__ x){
    size_t i = ((size_t)blockIdx.x * 256 + threadIdx.x) * 8;
    float4 a = *(const float4*)(x + i);
    float4 b = *(const float4*)(x + i + 4);
    uint4 H;
    H.x = packh(a.x, a.y); H.y = packh(a.z, a.w);
    H.z = packh(b.x, b.y); H.w = packh(b.z, b.w);
    *(uint4*)(g_Xh + i) = H;
}

// -------------------- transpose W (hi only, fp16) ----------------------------
__global__ __launch_bounds__(256) void splitw_kernel(const float* __restrict__ w){
    __shared__ float ws[64][65];
    const int n0 = blockIdx.x * 64, k0 = blockIdx.y * 64;
    #pragma unroll
    for(int i=0;i<4;i++){
        int e = i*256 + threadIdx.x;
        int r = e >> 4, c4 = (e & 15) * 4;
        float4 t = *(const float4*)(w + (size_t)(k0 + r) * 3072 + n0 + c4);
        ws[r][c4+0]=t.x; ws[r][c4+1]=t.y; ws[r][c4+2]=t.z; ws[r][c4+3]=t.w;
    }
    __syncthreads();
    int n = threadIdx.x >> 2, sg = (threadIdx.x & 3) * 16;
    unsigned H[8];
    #pragma unroll
    for(int j=0;j<8;j++)
        H[j] = packh(ws[sg + 2*j][n], ws[sg + 2*j + 1][n]);
    __half* dh = g_Wh + (size_t)(n0 + n) * 1024 + k0 + sg;
    *(uint4*)(dh)     = *(uint4*)(H);
    *(uint4*)(dh + 8) = *(uint4*)(H + 4);
}

// ------------------------------ QKV GEMM ------------------------------------
// grid (24, 32), 256 thr (8 warps as 4m x 2n, warp tile 64x64), CTA 256x128.
// Double-buffered cp.async. Stage s (49152 B): A +0 (32K), B +32K (16K).
// Epilogue staging 256*272=69632 B (reuses stages). GSM=98304.
#define GSM 98304

__global__ __launch_bounds__(256,2) void gemm_kernel(){
    extern __shared__ char sm[];
    const unsigned sb = su32(sm);
    const int tid = threadIdx.x, lane = tid & 31, wid = tid >> 5;
    const int wr = wid & 3, wc = wid >> 2;   // 4x2 warp grid, 64x64 each
    const int m0 = blockIdx.y * 256, n0 = blockIdx.x * 128;

    float acc[4][8][4];
    #pragma unroll
    for(int a=0;a<4;a++)
        #pragma unroll
        for(int b=0;b<8;b++)
            #pragma unroll
            for(int c=0;c<4;c++) acc[a][b][c]=0.0f;

    const int rr  = (lane & 7) + ((lane >> 3) & 1) * 8;
    const int csl = lane >> 4;

    // load-issue index: A 256 rows, B 128 rows, 8 chunks of 16B each.
    const int lr = tid >> 3, lch = tid & 7;   // lr 0..31

    #define G_ISSUE(c, st) do{ \
        const int k0_ = (c) * 64; \
        const unsigned base_ = sb + (st) * 49152; \
        _Pragma("unroll") \
        for(int j_ = 0; j_ < 8; j_++){ \
            int r_ = lr + j_*32; \
            cpa16(base_ + SWZ(r_*128 + lch*16), \
                  g_Xh + (size_t)(m0 + r_) * 1024 + k0_ + lch*8); \
        } \
        _Pragma("unroll") \
        for(int j_ = 0; j_ < 4; j_++){ \
            int r_ = lr + j_*32; \
            cpa16(base_ + 32768 + SWZ(r_*128 + lch*16), \
                  g_Wh + (size_t)(n0 + r_) * 1024 + k0_ + lch*8); \
        } \
        CP_COMMIT(); \
    }while(0)

    G_ISSUE(0, 0);

    for(int c = 0; c < 16; c++){
        if(c < 15){ G_ISSUE(c + 1, (c + 1) & 1); CP_WAIT1(); }
        else      { CP_WAIT0(); }
        __syncthreads();
        const unsigned base = sb + (c & 1) * 49152;

        #pragma unroll
        for(int ks = 0; ks < 4; ks++){
            const int cc2 = ks*2 + csl;
            unsigned ah[4][4], bh[4][4];
            #pragma unroll
            for(int mt = 0; mt < 4; mt++)
                ldsm4(ah[mt], base + SWZ((wr*64 + mt*16 + rr)*128 + cc2*16));
            #pragma unroll
            for(int g = 0; g < 4; g++)
                ldsm4(bh[g], base + 32768 + SWZ((wc*64 + g*16 + rr)*128 + cc2*16));
            #pragma unroll
            for(int g = 0; g < 4; g++)
                #pragma unroll
                for(int sub = 0; sub < 2; sub++){
                    const int nt = g*2 + sub;
                    #pragma unroll
                    for(int mt = 0; mt < 4; mt++)
                        mma16816(acc[mt][nt], ah[mt], bh[g][sub], bh[g][sub+2]);
                }
        }
        __syncthreads();
    }

    // Stage fp16 (hi only) into smem, then coalesced global writes.
    const int part = n0 >> 10;          // 0=K, 1=Q, 2=V
    const int h0   = (n0 & 1023) >> 6;  // 2 heads per 128-col tile
    const float sc = (part == 1) ? QF_ : 1.0f;
    __half* gh = (part == 0) ? g_Kh : (part == 1) ? g_Qh : g_Vsh;

    #pragma unroll
    for(int mt = 0; mt < 4; mt++)
        #pragma unroll
        for(int nt = 0; nt < 8; nt++){
            const int r0 = wr*64 + mt*16 + (lane >> 2);
            const int cc = wc*64 + nt*8 + (lane & 3)*2;
            *(unsigned*)(sm + r0*272 + cc*2)     = packh(acc[mt][nt][0]*sc, acc[mt][nt][1]*sc);
            *(unsigned*)(sm + (r0+8)*272 + cc*2) = packh(acc[mt][nt][2]*sc, acc[mt][nt][3]*sc);
        }
    __syncthreads();

    #pragma unroll
    for(int j = 0; j < 16; j++){
        int i = tid + j*256;
        int r = i >> 4, cc = i & 15;
        int gr = m0 + r;
        int b = gr >> 11, s = gr & 2047;
        int h = h0 + (cc >> 3);
        size_t off = (((size_t)(b*16 + h)*2048 + s)*64) + (size_t)(cc & 7)*8;
        *(uint4*)(gh + off) = *(uint4*)(sm + r*272 + cc*16);
    }
}

// ------------------------------ attention -----------------------------------
// grid (16, 64): (qtile, bh). 256 thr (8 warps, 16 q-rows each). Pure fp16.
// smem: QH @0 (16K). Stage s (16384 B each) @16384: KH +0, VH +8K.
// ASM = 16384 + 32768 = 49152.
#define ASM 49152

__global__ __launch_bounds__(256,2) void attn_kernel(float* __restrict__ out){
    extern __shared__ char sm[];
    const unsigned sb = su32(sm);
    const int tid = threadIdx.x, lane = tid & 31, w = tid >> 5;
    const int qt = blockIdx.x, bh = blockIdx.y;
    const int h = bh & 15, b = bh >> 4;
    const int i0 = qt * 128;
    const size_t ib = (size_t)bh * 131072;

    const float slope = exp2f(-0.5f * (float)(h + 1));
    const float c2 = slope * 1.4426950408889634f;

    // load Q tile (plain stores, swizzled)
    #pragma unroll
    for(int j = 0; j < 4; j++){
        int i = tid + j*256;
        int r = i >> 3, ch = i & 7;
        unsigned o = SWZ(r*128 + ch*16);
        *(uint4*)(sm + o) = *(const uint4*)(g_Qh + ib + (size_t)(i0 + r)*64 + ch*8);
    }

    int kt0 = 0;
    while(kt0 < 31 && c2 * (float)(1984 - 64*kt0) > 20.0f) kt0++;
    const int nch = 32 - kt0;

    const int lr = tid >> 3, lch = tid & 7;     // lr 0..31
    #define A_ISSUE(kt, st) do{ \
        const int j0_ = (kt) * 64; \
        const unsigned base_ = sb + 16384 + (st) * 16384; \
        _Pragma("unroll") \
        for(int j_ = 0; j_ < 2; j_++){ \
            int r_ = lr + j_*32; \
            unsigned o_ = SWZ(r_*128 + lch*16); \
            size_t gx_ = ib + (size_t)(j0_ + r_)*64 + lch*8; \
            cpa16(base_ + o_,        g_Kh  + gx_); \
            cpa16(base_ + 8192 + o_, g_Vsh + gx_); \
        } \
        CP_COMMIT(); \
    }while(0)

    A_ISSUE(kt0, 0);
    __syncthreads();   // Q visible

    const int rr  = (lane & 7) + ((lane >> 3) & 1) * 8;
    const int csl = lane >> 4;

    unsigned qh[4][4];
    #pragma unroll
    for(int ks = 0; ks < 4; ks++)
        ldsm4(qh[ks], sb + SWZ((w*16 + rr)*128 + (ks*2 + csl)*16));

    float o_[8][4];
    #pragma unroll
    for(int a=0;a<8;a++)
        #pragma unroll
        for(int e=0;e<4;e++) o_[a][e]=0.0f;
    float l0 = 0.0f, l1 = 0.0f;

    for(int ci = 0; ci < nch; ci++){
        const int kt = kt0 + ci;
        const int j0 = kt * 64;
        if(ci + 1 < nch){ A_ISSUE(kt + 1, (ci + 1) & 1); CP_WAIT1(); }
        else            { CP_WAIT0(); }
        __syncthreads();
        const unsigned base = sb + 16384 + (ci & 1) * 16384;

        // S = Q @ K^T  (pure fp16)
        float s_[8][4];
        #pragma unroll
        for(int a=0;a<8;a++)
            #pragma unroll
            for(int e=0;e<4;e++) s_[a][e]=0.0f;
        #pragma unroll
        for(int ks = 0; ks < 4; ks++){
            unsigned kbh[4][4];
            #pragma unroll
            for(int g = 0; g < 4; g++)
                ldsm4(kbh[g], base + SWZ((g*16 + rr)*128 + (ks*2 + csl)*16));
            #pragma unroll
            for(int g = 0; g < 4; g++)
                #pragma unroll
                for(int sub = 0; sub < 2; sub++)
                    mma16816(s_[g*2 + sub], qh[ks], kbh[g][sub], kbh[g][sub+2]);
        }

        // exp2 with analytic shift; build P fragments (fp16)
        unsigned ph[4][4];
        #pragma unroll
        for(int nt = 0; nt < 8; nt++){
            const float jb = (float)(j0 + nt*8 + (lane & 3)*2 - 2047);
            float p0 = ex2f(fmaf(c2, jb,        s_[nt][0]));
            float p1 = ex2f(fmaf(c2, jb + 1.0f, s_[nt][1]));
            float p2 = ex2f(fmaf(c2, jb,        s_[nt][2]));
            float p3 = ex2f(fmaf(c2, jb + 1.0f, s_[nt][3]));
            l0 += p0 + p1;
            l1 += p2 + p3;
            const int kk = nt >> 1, od = nt & 1;
            ph[kk][od ? 2 : 0] = packh(p0, p1);
            ph[kk][od ? 3 : 1] = packh(p2, p3);
        }

        // O += P @ V  (V stored [s][d]; B-fragments via ldmatrix.trans; fp16)
        #pragma unroll
        for(int kk = 0; kk < 4; kk++){
            unsigned vbh[4][4];
            #pragma unroll
            for(int g = 0; g < 4; g++)
                ldsm4t(vbh[g], base + 8192 + SWZ((kk*16 + rr)*128 + (g*2 + csl)*16));
            #pragma unroll
            for(int g = 0; g < 4; g++)
                #pragma unroll
                for(int sub = 0; sub < 2; sub++)
                    mma16816(o_[g*2 + sub], ph[kk], vbh[g][2*sub], vbh[g][2*sub+1]);
        }
        __syncthreads();
    }

    // reduce l within quads
    l0 += __shfl_xor_sync(0xffffffffu, l0, 1);
    l0 += __shfl_xor_sync(0xffffffffu, l0, 2);
    l1 += __shfl_xor_sync(0xffffffffu, l1, 1);
    l1 += __shfl_xor_sync(0xffffffffu, l1, 2);
    const float inv0 = 1.0f / l0, inv1 = 1.0f / l1;

    const int r0g = i0 + w*16 + (lane >> 2);
    float* op0 = out + ((size_t)b*2048 + r0g)*1024 + h*64 + (lane & 3)*2;
    float* op1 = out + ((size_t)b*2048 + r0g + 8)*1024 + h*64 + (lane & 3)*2;
    #pragma unroll
    for(int nt = 0; nt < 8; nt++){
        *(float2*)(op0 + nt*8) = make_float2(o_[nt][0]*inv0, o_[nt][1]*inv0);
        *(float2*)(op1 + nt*8) = make_float2(o_[nt][2]*inv1, o_[nt][3]*inv1);
    }
}

// ------------------------------- launch --------------------------------------
extern "C" void kernel_launch(void* const* d_in, const int* in_sizes, int n_in,
                              void* d_out, int out_size)
{
    const float* x = (const float*)d_in[0];
    const float* w = (const float*)d_in[1];
    float* out = (float*)d_out;
    (void)in_sizes; (void)n_in; (void)out_size;

    splitx_kernel<<<4096, 256>>>(x);
    splitw_kernel<<<dim3(48, 16), 256>>>(w);

    cudaFuncSetAttribute(gemm_kernel, cudaFuncAttributeMaxDynamicSharedMemorySize, GSM);
    gemm_kernel<<<dim3(24, 32), 256, GSM>>>();

    cudaFuncSetAttribute(attn_kernel, cudaFuncAttributeMaxDynamicSharedMemorySize, ASM);
    attn_kernel<<<dim3(16, 64), 256, ASM>>>(out);
}

// round 15
// speedup vs baseline: 2.4652x; 2.4652x over previous
#include <cuda_runtime.h>
#include <cuda_fp16.h>
#include <math.h>

#define QF_ 0.04508422002777998f   // log2(e)/32

// ------------------------- device scratch (no allocs) ----------------------
__device__ __half g_Xh[(size_t)8192*1024];
__device__ __half g_Wh[(size_t)3072*1024];   // W^T [n][k]
__device__ __half g_Qh[(size_t)64*2048*64];  // [bh][s][d] (pre-scaled by QF)
__device__ __half g_Kh[(size_t)64*2048*64];
__device__ __half g_Vsh[(size_t)64*2048*64]; // [bh][s][d]

// ------------------------------ helpers ------------------------------------
__device__ __forceinline__ unsigned su32(const void* p){
    unsigned a;
    asm("{ .reg .u64 t; cvta.to.shared.u64 t, %1; cvt.u32.u64 %0, t; }":"=r"(a):"l"(p));
    return a;
}
#define SWZ(o) ((unsigned)(o) ^ ((((unsigned)(o)) >> 3) & 0x70))

__device__ __forceinline__ void cpa16(unsigned dst, const void* src){
    asm volatile("cp.async.cg.shared.global [%0], [%1], 16;"::"r"(dst),"l"(src));
}
#define CP_COMMIT() asm volatile("cp.async.commit_group;" ::: "memory")
#define CP_WAIT2()  asm volatile("cp.async.wait_group 2;" ::: "memory")
#define CP_WAIT1()  asm volatile("cp.async.wait_group 1;" ::: "memory")
#define CP_WAIT0()  asm volatile("cp.async.wait_group 0;" ::: "memory")

__device__ __forceinline__ void ldsm4(unsigned* r, unsigned a){
    asm volatile("ldmatrix.sync.aligned.m8n8.x4.shared.b16 {%0,%1,%2,%3}, [%4];"
                 : "=r"(r[0]),"=r"(r[1]),"=r"(r[2]),"=r"(r[3]) : "r"(a));
}
__device__ __forceinline__ void ldsm4t(unsigned* r, unsigned a){
    asm volatile("ldmatrix.sync.aligned.m8n8.x4.trans.shared.b16 {%0,%1,%2,%3}, [%4];"
                 : "=r"(r[0]),"=r"(r[1]),"=r"(r[2]),"=r"(r[3]) : "r"(a));
}
__device__ __forceinline__ void mma16816(float* d, const unsigned* a, unsigned b0, unsigned b1){
    asm volatile("mma.sync.aligned.m16n8k16.row.col.f32.f16.f16.f32 "
                 "{%0,%1,%2,%3},{%4,%5,%6,%7},{%8,%9},{%0,%1,%2,%3};"
                 : "+f"(d[0]),"+f"(d[1]),"+f"(d[2]),"+f"(d[3])
                 : "r"(a[0]),"r"(a[1]),"r"(a[2]),"r"(a[3]),"r"(b0),"r"(b1));
}
__device__ __forceinline__ float ex2f(float x){
    float r; asm("ex2.approx.ftz.f32 %0, %1;":"=f"(r):"f"(x)); return r;
}
__device__ __forceinline__ unsigned packh(float a, float b){
    __half2 h = __floats2half2_rn(a, b);
    return *(unsigned*)&h;
}

// ---------------------------- split X (hi only) ------------------------------
__global__ __launch_bounds__(256) void splitx_kernel(const float* __restrict__ x){
    size_t i = ((size_t)blockIdx.x * 256 + threadIdx.x) * 8;
    float4 a = *(const float4*)(x + i);
    float4 b = *(const float4*)(x + i + 4);
    uint4 H;
    H.x = packh(a.x, a.y); H.y = packh(a.z, a.w);
    H.z = packh(b.x, b.y); H.w = packh(b.z, b.w);
    *(uint4*)(g_Xh + i) = H;
}

// -------------------- transpose W (hi only, fp16) ----------------------------
__global__ __launch_bounds__(256) void splitw_kernel(const float* __restrict__ w){
    __shared__ float ws[64][65];
    const int n0 = blockIdx.x * 64, k0 = blockIdx.y * 64;
    #pragma unroll
    for(int i=0;i<4;i++){
        int e = i*256 + threadIdx.x;
        int r = e >> 4, c4 = (e & 15) * 4;
        float4 t = *(const float4*)(w + (size_t)(k0 + r) * 3072 + n0 + c4);
        ws[r][c4+0]=t.x; ws[r][c4+1]=t.y; ws[r][c4+2]=t.z; ws[r][c4+3]=t.w;
    }
    __syncthreads();
    int n = threadIdx.x >> 2, sg = (threadIdx.x & 3) * 16;
    unsigned H[8];
    #pragma unroll
    for(int j=0;j<8;j++)
        H[j] = packh(ws[sg + 2*j][n], ws[sg + 2*j + 1][n]);
    __half* dh = g_Wh + (size_t)(n0 + n) * 1024 + k0 + sg;
    *(uint4*)(dh)     = *(uint4*)(H);
    *(uint4*)(dh + 8) = *(uint4*)(H + 4);
}

// ------------------------------ QKV GEMM ------------------------------------
// grid (24, 64), 256 thr, CTA 128x128, warp tile 32x64 (R10 shape).
// Triple-buffered cp.async. Stage s (32768 B each): AH +0 (16K), BH +16K.
// Epilogue staging 34816 B reuses stage area. GSM = 3*32768 = 98304.
#define GSM 98304

__global__ __launch_bounds__(256) void gemm_kernel(){
    extern __shared__ char sm[];
    const unsigned sb = su32(sm);
    const int tid = threadIdx.x, lane = tid & 31, wid = tid >> 5;
    const int wr = wid & 3, wc = wid >> 2;
    const int m0 = blockIdx.y * 128, n0 = blockIdx.x * 128;

    float acc[2][8][4];
    #pragma unroll
    for(int a=0;a<2;a++)
        #pragma unroll
        for(int b=0;b<8;b++)
            #pragma unroll
            for(int c=0;c<4;c++) acc[a][b][c]=0.0f;

    const int rr  = (lane & 7) + ((lane >> 3) & 1) * 8;
    const int csl = lane >> 4;

    // load-issue index (constant across stages)
    const int lr = tid >> 3, lch = tid & 7;
    const unsigned lo_sw[4] = { SWZ((lr     )*128 + lch*16), SWZ((lr + 32)*128 + lch*16),
                                SWZ((lr + 64)*128 + lch*16), SWZ((lr + 96)*128 + lch*16) };

    #define G_ISSUE(c, st) do{ \
        const int k0_ = (c) * 64; \
        const unsigned base_ = sb + (st) * 32768; \
        _Pragma("unroll") \
        for(int j_ = 0; j_ < 4; j_++){ \
            int r_ = lr + j_*32; \
            unsigned o_ = lo_sw[j_]; \
            cpa16(base_ + o_,         g_Xh + (size_t)(m0 + r_) * 1024 + k0_ + lch*8); \
            cpa16(base_ + 16384 + o_, g_Wh + (size_t)(n0 + r_) * 1024 + k0_ + lch*8); \
        } \
        CP_COMMIT(); \
    }while(0)

    G_ISSUE(0, 0);
    G_ISSUE(1, 1);

    #pragma unroll 1
    for(int c = 0; c < 16; c++){
        if(c + 2 < 16){ G_ISSUE(c + 2, (c + 2) % 3); CP_WAIT2(); }
        else if(c + 1 < 16){ CP_WAIT1(); }
        else { CP_WAIT0(); }
        __syncthreads();
        const unsigned base = sb + (c % 3) * 32768;

        #pragma unroll
        for(int ks = 0; ks < 4; ks++){
            unsigned ah[2][4];
            const int cc2 = ks*2 + csl;
            #pragma unroll
            for(int mt = 0; mt < 2; mt++)
                ldsm4(ah[mt], base + SWZ((wr*32 + mt*16 + rr)*128 + cc2*16));
            #pragma unroll
            for(int hf = 0; hf < 2; hf++){
                unsigned bh[2][4];
                #pragma unroll
                for(int g = 0; g < 2; g++)
                    ldsm4(bh[g], base + 16384 + SWZ((wc*64 + hf*32 + g*16 + rr)*128 + cc2*16));
                #pragma unroll
                for(int g = 0; g < 2; g++)
                    #pragma unroll
                    for(int sub = 0; sub < 2; sub++){
                        const int nt = hf*4 + g*2 + sub;
                        #pragma unroll
                        for(int mt = 0; mt < 2; mt++)
                            mma16816(acc[mt][nt], ah[mt], bh[g][sub], bh[g][sub+2]);
                    }
            }
        }
        __syncthreads();
    }

    // Stage fp16 (hi only) into smem, then coalesced global writes.
    const int part = n0 >> 10;          // 0=K, 1=Q, 2=V
    const int h0   = (n0 & 1023) >> 6;
    const float sc = (part == 1) ? QF_ : 1.0f;
    __half* gh = (part == 0) ? g_Kh : (part == 1) ? g_Qh : g_Vsh;

    #pragma unroll
    for(int mt = 0; mt < 2; mt++)
        #pragma unroll
        for(int nt = 0; nt < 8; nt++){
            const int r0 = wr*32 + mt*16 + (lane >> 2);
            const int cc = wc*64 + nt*8 + (lane & 3)*2;
            *(unsigned*)(sm + r0*272 + cc*2)     = packh(acc[mt][nt][0]*sc, acc[mt][nt][1]*sc);
            *(unsigned*)(sm + (r0+8)*272 + cc*2) = packh(acc[mt][nt][2]*sc, acc[mt][nt][3]*sc);
        }
    __syncthreads();

    #pragma unroll
    for(int j = 0; j < 8; j++){
        int i = tid + j*256;
        int r = i >> 4, cc = i & 15;
        int gr = m0 + r;
        int b = gr >> 11, s = gr & 2047;
        int h = h0 + (cc >> 3);
        size_t off = (((size_t)(b*16 + h)*2048 + s)*64) + (size_t)(cc & 7)*8;
        *(uint4*)(gh + off) = *(uint4*)(sm + r*272 + cc*16);
    }
}

// ------------------------------ attention -----------------------------------
// grid (16, 64): (qtile, bh'). Heavy heads scheduled FIRST: h = 15 - (bh'&15).
// 256 thr (8 warps, 16 q-rows each). Pure fp16.
// smem: QH @0 (16K). Stage s (16384 B each) @16384: KH +0, VH +8K.
// ASM = 16384 + 32768 = 49152.
#define ASM 49152

__global__ __launch_bounds__(256,2) void attn_kernel(float* __restrict__ out){
    extern __shared__ char sm[];
    const unsigned sb = su32(sm);
    const int tid = threadIdx.x, lane = tid & 31, w = tid >> 5;
    const int qt = blockIdx.x;
    const int h = 15 - ((int)blockIdx.y & 15);   // heavy heads first
    const int b = (int)blockIdx.y >> 4;
    const int bh = b * 16 + h;
    const int i0 = qt * 128;
    const size_t ib = (size_t)bh * 131072;

    const float slope = exp2f(-0.5f * (float)(h + 1));
    const float c2 = slope * 1.4426950408889634f;

    // load Q tile (plain stores, swizzled)
    #pragma unroll
    for(int j = 0; j < 4; j++){
        int i = tid + j*256;
        int r = i >> 3, ch = i & 7;
        unsigned o = SWZ(r*128 + ch*16);
        *(uint4*)(sm + o) = *(const uint4*)(g_Qh + ib + (size_t)(i0 + r)*64 + ch*8);
    }

    int kt0 = 0;
    while(kt0 < 31 && c2 * (float)(1984 - 64*kt0) > 20.0f) kt0++;
    const int nch = 32 - kt0;

    const int lr = tid >> 3, lch = tid & 7;     // lr 0..31
    #define A_ISSUE(kt, st) do{ \
        const int j0_ = (kt) * 64; \
        const unsigned base_ = sb + 16384 + (st) * 16384; \
        _Pragma("unroll") \
        for(int j_ = 0; j_ < 2; j_++){ \
            int r_ = lr + j_*32; \
            unsigned o_ = SWZ(r_*128 + lch*16); \
            size_t gx_ = ib + (size_t)(j0_ + r_)*64 + lch*8; \
            cpa16(base_ + o_,        g_Kh  + gx_); \
            cpa16(base_ + 8192 + o_, g_Vsh + gx_); \
        } \
        CP_COMMIT(); \
    }while(0)

    A_ISSUE(kt0, 0);
    __syncthreads();   // Q visible

    const int rr  = (lane & 7) + ((lane >> 3) & 1) * 8;
    const int csl = lane >> 4;

    unsigned qh[4][4];
    #pragma unroll
    for(int ks = 0; ks < 4; ks++)
        ldsm4(qh[ks], sb + SWZ((w*16 + rr)*128 + (ks*2 + csl)*16));

    float o_[8][4];
    #pragma unroll
    for(int a=0;a<8;a++)
        #pragma unroll
        for(int e=0;e<4;e++) o_[a][e]=0.0f;
    float l0 = 0.0f, l1 = 0.0f;

    for(int ci = 0; ci < nch; ci++){
        const int kt = kt0 + ci;
        const int j0 = kt * 64;
        if(ci + 1 < nch){ A_ISSUE(kt + 1, (ci + 1) & 1); CP_WAIT1(); }
        else            { CP_WAIT0(); }
        __syncthreads();
        const unsigned base = sb + 16384 + (ci & 1) * 16384;

        // S = Q @ K^T  (pure fp16)
        float s_[8][4];
        #pragma unroll
        for(int a=0;a<8;a++)
            #pragma unroll
            for(int e=0;e<4;e++) s_[a][e]=0.0f;
        #pragma unroll
        for(int ks = 0; ks < 4; ks++){
            unsigned kbh[4][4];
            #pragma unroll
            for(int g = 0; g < 4; g++)
                ldsm4(kbh[g], base + SWZ((g*16 + rr)*128 + (ks*2 + csl)*16));
            #pragma unroll
            for(int g = 0; g < 4; g++)
                #pragma unroll
                for(int sub = 0; sub < 2; sub++)
                    mma16816(s_[g*2 + sub], qh[ks], kbh[g][sub], kbh[g][sub+2]);
        }

        // exp2 with analytic shift; build P fragments (fp16)
        unsigned ph[4][4];
        #pragma unroll
        for(int nt = 0; nt < 8; nt++){
            const float jb = (float)(j0 + nt*8 + (lane & 3)*2 - 2047);
            float p0 = ex2f(fmaf(c2, jb,        s_[nt][0]));
            float p1 = ex2f(fmaf(c2, jb + 1.0f, s_[nt][1]));
            float p2 = ex2f(fmaf(c2, jb,        s_[nt][2]));
            float p3 = ex2f(fmaf(c2, jb + 1.0f, s_[nt][3]));
            l0 += p0 + p1;
            l1 += p2 + p3;
            const int kk = nt >> 1, od = nt & 1;
            ph[kk][od ? 2 : 0] = packh(p0, p1);
            ph[kk][od ? 3 : 1] = packh(p2, p3);
        }

        // O += P @ V  (V stored [s][d]; B-fragments via ldmatrix.trans; fp16)
        #pragma unroll
        for(int kk = 0; kk < 4; kk++){
            unsigned vbh[4][4];
            #pragma unroll
            for(int g = 0; g < 4; g++)
                ldsm4t(vbh[g], base + 8192 + SWZ((kk*16 + rr)*128 + (g*2 + csl)*16));
            #pragma unroll
            for(int g = 0; g < 4; g++)
                #pragma unroll
                for(int sub = 0; sub < 2; sub++)
                    mma16816(o_[g*2 + sub], ph[kk], vbh[g][2*sub], vbh[g][2*sub+1]);
        }
        __syncthreads();
    }

    // reduce l within quads
    l0 += __shfl_xor_sync(0xffffffffu, l0, 1);
    l0 += __shfl_xor_sync(0xffffffffu, l0, 2);
    l1 += __shfl_xor_sync(0xffffffffu, l1, 1);
    l1 += __shfl_xor_sync(0xffffffffu, l1, 2);
    const float inv0 = 1.0f / l0, inv1 = 1.0f / l1;

    const int r0g = i0 + w*16 + (lane >> 2);
    float* op0 = out + ((size_t)b*2048 + r0g)*1024 + h*64 + (lane & 3)*2;
    float* op1 = out + ((size_t)b*2048 + r0g + 8)*1024 + h*64 + (lane & 3)*2;
    #pragma unroll
    for(int nt = 0; nt < 8; nt++){
        *(float2*)(op0 + nt*8) = make_float2(o_[nt][0]*inv0, o_[nt][1]*inv0);
        *(float2*)(op1 + nt*8) = make_float2(o_[nt][2]*inv1, o_[nt][3]*inv1);
    }
}

// ------------------------------- launch --------------------------------------
extern "C" void kernel_launch(void* const* d_in, const int* in_sizes, int n_in,
                              void* d_out, int out_size)
{
    const float* x = (const float*)d_in[0];
    const float* w = (const float*)d_in[1];
    float* out = (float*)d_out;
    (void)in_sizes; (void)n_in; (void)out_size;

    splitx_kernel<<<4096, 256>>>(x);
    splitw_kernel<<<dim3(48, 16), 256>>>(w);

    cudaFuncSetAttribute(gemm_kernel, cudaFuncAttributeMaxDynamicSharedMemorySize, GSM);
    gemm_kernel<<<dim3(24, 64), 256, GSM>>>();

    cudaFuncSetAttribute(attn_kernel, cudaFuncAttributeMaxDynamicSharedMemorySize, ASM);
    attn_kernel<<<dim3(16, 64), 256, ASM>>>(out);
}

// round 16
// speedup vs baseline: 2.5217x; 1.0229x over previous
#include <cuda_runtime.h>
#include <cuda_fp16.h>
#include <math.h>

#define QF_ 0.04508422002777998f   // log2(e)/32

// ------------------------- device scratch (no allocs) ----------------------
__device__ __half g_Xh[(size_t)8192*1024];
__device__ __half g_Wh[(size_t)3072*1024];   // W^T [n][k]
__device__ __half g_Qh[(size_t)64*2048*64];  // [bh][s][d] (pre-scaled by QF)
__device__ __half g_Kh[(size_t)64*2048*64];
__device__ __half g_Vsh[(size_t)64*2048*64]; // [bh][s][d]

// ------------------------------ helpers ------------------------------------
__device__ __forceinline__ unsigned su32(const void* p){
    unsigned a;
    asm("{ .reg .u64 t; cvta.to.shared.u64 t, %1; cvt.u32.u64 %0, t; }":"=r"(a):"l"(p));
    return a;
}
#define SWZ(o) ((unsigned)(o) ^ ((((unsigned)(o)) >> 3) & 0x70))

__device__ __forceinline__ void cpa16(unsigned dst, const void* src){
    asm volatile("cp.async.cg.shared.global [%0], [%1], 16;"::"r"(dst),"l"(src));
}
#define CP_COMMIT() asm volatile("cp.async.commit_group;" ::: "memory")
#define CP_WAIT1()  asm volatile("cp.async.wait_group 1;" ::: "memory")
#define CP_WAIT0()  asm volatile("cp.async.wait_group 0;" ::: "memory")

__device__ __forceinline__ void ldsm4(unsigned* r, unsigned a){
    asm volatile("ldmatrix.sync.aligned.m8n8.x4.shared.b16 {%0,%1,%2,%3}, [%4];"
                 : "=r"(r[0]),"=r"(r[1]),"=r"(r[2]),"=r"(r[3]) : "r"(a));
}
__device__ __forceinline__ void ldsm4t(unsigned* r, unsigned a){
    asm volatile("ldmatrix.sync.aligned.m8n8.x4.trans.shared.b16 {%0,%1,%2,%3}, [%4];"
                 : "=r"(r[0]),"=r"(r[1]),"=r"(r[2]),"=r"(r[3]) : "r"(a));
}
__device__ __forceinline__ void mma16816(float* d, const unsigned* a, unsigned b0, unsigned b1){
    asm volatile("mma.sync.aligned.m16n8k16.row.col.f32.f16.f16.f32 "
                 "{%0,%1,%2,%3},{%4,%5,%6,%7},{%8,%9},{%0,%1,%2,%3};"
                 : "+f"(d[0]),"+f"(d[1]),"+f"(d[2]),"+f"(d[3])
                 : "r"(a[0]),"r"(a[1]),"r"(a[2]),"r"(a[3]),"r"(b0),"r"(b1));
}
__device__ __forceinline__ float ex2f(float x){
    float r; asm("ex2.approx.ftz.f32 %0, %1;":"=f"(r):"f"(x)); return r;
}
__device__ __forceinline__ unsigned packh(float a, float b){
    __half2 h = __floats2half2_rn(a, b);
    return *(unsigned*)&h;
}

// ---------------------------- split X (hi only) ------------------------------
__global__ __launch_bounds__(256) void splitx_kernel(const float* __restrict__ x){
    size_t i = ((size_t)blockIdx.x * 256 + threadIdx.x) * 8;
    float4 a = *(const float4*)(x + i);
    float4 b = *(const float4*)(x + i + 4);
    uint4 H;
    H.x = packh(a.x, a.y); H.y = packh(a.z, a.w);
    H.z = packh(b.x, b.y); H.w = packh(b.z, b.w);
    *(uint4*)(g_Xh + i) = H;
}

// -------------------- transpose W (hi only, fp16) ----------------------------
__global__ __launch_bounds__(256) void splitw_kernel(const float* __restrict__ w){
    __shared__ float ws[64][65];
    const int n0 = blockIdx.x * 64, k0 = blockIdx.y * 64;
    #pragma unroll
    for(int i=0;i<4;i++){
        int e = i*256 + threadIdx.x;
        int r = e >> 4, c4 = (e & 15) * 4;
        float4 t = *(const float4*)(w + (size_t)(k0 + r) * 3072 + n0 + c4);
        ws[r][c4+0]=t.x; ws[r][c4+1]=t.y; ws[r][c4+2]=t.z; ws[r][c4+3]=t.w;
    }
    __syncthreads();
    int n = threadIdx.x >> 2, sg = (threadIdx.x & 3) * 16;
    unsigned H[8];
    #pragma unroll
    for(int j=0;j<8;j++)
        H[j] = packh(ws[sg + 2*j][n], ws[sg + 2*j + 1][n]);
    __half* dh = g_Wh + (size_t)(n0 + n) * 1024 + k0 + sg;
    *(uint4*)(dh)     = *(uint4*)(H);
    *(uint4*)(dh + 8) = *(uint4*)(H + 4);
}

// ------------------------------ QKV GEMM ------------------------------------
// grid (24, 64), 256 thr, CTA 128x128, warp tile 32x64 (R10 proven shape).
// Double-buffered cp.async. Stage s (32768 B each): AH +0 (16K), BH +16K.
// Epilogue staging 34816 B reuses stage area. GSM=65536 (2 CTAs/SM).
#define GSM 65536

__global__ __launch_bounds__(256) void gemm_kernel(){
    extern __shared__ char sm[];
    const unsigned sb = su32(sm);
    const int tid = threadIdx.x, lane = tid & 31, wid = tid >> 5;
    const int wr = wid & 3, wc = wid >> 2;
    const int m0 = blockIdx.y * 128, n0 = blockIdx.x * 128;

    float acc[2][8][4];
    #pragma unroll
    for(int a=0;a<2;a++)
        #pragma unroll
        for(int b=0;b<8;b++)
            #pragma unroll
            for(int c=0;c<4;c++) acc[a][b][c]=0.0f;

    const int rr  = (lane & 7) + ((lane >> 3) & 1) * 8;
    const int csl = lane >> 4;

    const int lr = tid >> 3, lch = tid & 7;
    const unsigned lo_sw[4] = { SWZ((lr     )*128 + lch*16), SWZ((lr + 32)*128 + lch*16),
                                SWZ((lr + 64)*128 + lch*16), SWZ((lr + 96)*128 + lch*16) };

    #define G_ISSUE(c, st) do{ \
        const int k0_ = (c) * 64; \
        const unsigned base_ = sb + (st) * 32768; \
        _Pragma("unroll") \
        for(int j_ = 0; j_ < 4; j_++){ \
            int r_ = lr + j_*32; \
            unsigned o_ = lo_sw[j_]; \
            cpa16(base_ + o_,         g_Xh + (size_t)(m0 + r_) * 1024 + k0_ + lch*8); \
            cpa16(base_ + 16384 + o_, g_Wh + (size_t)(n0 + r_) * 1024 + k0_ + lch*8); \
        } \
        CP_COMMIT(); \
    }while(0)

    G_ISSUE(0, 0);

    for(int c = 0; c < 16; c++){
        if(c < 15){ G_ISSUE(c + 1, (c + 1) & 1); CP_WAIT1(); }
        else      { CP_WAIT0(); }
        __syncthreads();
        const unsigned base = sb + (c & 1) * 32768;

        #pragma unroll
        for(int ks = 0; ks < 4; ks++){
            unsigned ah[2][4];
            const int cc2 = ks*2 + csl;
            #pragma unroll
            for(int mt = 0; mt < 2; mt++)
                ldsm4(ah[mt], base + SWZ((wr*32 + mt*16 + rr)*128 + cc2*16));
            #pragma unroll
            for(int hf = 0; hf < 2; hf++){
                unsigned bh[2][4];
                #pragma unroll
                for(int g = 0; g < 2; g++)
                    ldsm4(bh[g], base + 16384 + SWZ((wc*64 + hf*32 + g*16 + rr)*128 + cc2*16));
                #pragma unroll
                for(int g = 0; g < 2; g++)
                    #pragma unroll
                    for(int sub = 0; sub < 2; sub++){
                        const int nt = hf*4 + g*2 + sub;
                        #pragma unroll
                        for(int mt = 0; mt < 2; mt++)
                            mma16816(acc[mt][nt], ah[mt], bh[g][sub], bh[g][sub+2]);
                    }
            }
        }
        __syncthreads();
    }

    const int part = n0 >> 10;          // 0=K, 1=Q, 2=V
    const int h0   = (n0 & 1023) >> 6;
    const float sc = (part == 1) ? QF_ : 1.0f;
    __half* gh = (part == 0) ? g_Kh : (part == 1) ? g_Qh : g_Vsh;

    #pragma unroll
    for(int mt = 0; mt < 2; mt++)
        #pragma unroll
        for(int nt = 0; nt < 8; nt++){
            const int r0 = wr*32 + mt*16 + (lane >> 2);
            const int cc = wc*64 + nt*8 + (lane & 3)*2;
            *(unsigned*)(sm + r0*272 + cc*2)     = packh(acc[mt][nt][0]*sc, acc[mt][nt][1]*sc);
            *(unsigned*)(sm + (r0+8)*272 + cc*2) = packh(acc[mt][nt][2]*sc, acc[mt][nt][3]*sc);
        }
    __syncthreads();

    #pragma unroll
    for(int j = 0; j < 8; j++){
        int i = tid + j*256;
        int r = i >> 4, cc = i & 15;
        int gr = m0 + r;
        int b = gr >> 11, s = gr & 2047;
        int h = h0 + (cc >> 3);
        size_t off = (((size_t)(b*16 + h)*2048 + s)*64) + (size_t)(cc & 7)*8;
        *(uint4*)(gh + off) = *(uint4*)(sm + r*272 + cc*16);
    }
}

// ------------------------------ attention -----------------------------------
// grid (16, 64): (qtile, bh'). Heavy heads first: h = 15 - (bh'&15).
// 256 thr (8 warps, 16 q-rows each). Pure fp16.
// 3-stage cp.async ring, ONE barrier per chunk:
//   per iter: wait_group -> sync -> issue(ci+2) -> compute(ci).
//   sync at ci guarantees compute(ci-1) done; stage (ci+2)%3 == (ci-1)%3 free.
// smem: QH @0 (16K). Stages @16384, 16384 B each: KH +0, VH +8K.
// ASM = 16384 + 3*16384 = 65536 (2 CTAs/SM).
#define ASM 65536

__global__ __launch_bounds__(256,2) void attn_kernel(float* __restrict__ out){
    extern __shared__ char sm[];
    const unsigned sb = su32(sm);
    const int tid = threadIdx.x, lane = tid & 31, w = tid >> 5;
    const int qt = blockIdx.x;
    const int h = 15 - ((int)blockIdx.y & 15);   // heavy heads first
    const int b = (int)blockIdx.y >> 4;
    const int bh = b * 16 + h;
    const int i0 = qt * 128;
    const size_t ib = (size_t)bh * 131072;

    const float slope = exp2f(-0.5f * (float)(h + 1));
    const float c2 = slope * 1.4426950408889634f;

    int kt0 = 0;
    while(kt0 < 31 && c2 * (float)(1984 - 64*kt0) > 20.0f) kt0++;
    const int nch = 32 - kt0;

    const int lr = tid >> 3, lch = tid & 7;     // lr 0..31
    #define A_ISSUE(kt, st) do{ \
        const int j0_ = (kt) * 64; \
        const unsigned base_ = sb + 16384 + (st) * 16384; \
        _Pragma("unroll") \
        for(int j_ = 0; j_ < 2; j_++){ \
            int r_ = lr + j_*32; \
            unsigned o_ = SWZ(r_*128 + lch*16); \
            size_t gx_ = ib + (size_t)(j0_ + r_)*64 + lch*8; \
            cpa16(base_ + o_,        g_Kh  + gx_); \
            cpa16(base_ + 8192 + o_, g_Vsh + gx_); \
        } \
        CP_COMMIT(); \
    }while(0)

    // prefetch stages 0,1, then load Q (plain stores) and sync once.
    A_ISSUE(kt0, 0);
    if(nch > 1) A_ISSUE(kt0 + 1, 1);

    #pragma unroll
    for(int j = 0; j < 4; j++){
        int i = tid + j*256;
        int r = i >> 3, ch = i & 7;
        unsigned o = SWZ(r*128 + ch*16);
        *(uint4*)(sm + o) = *(const uint4*)(g_Qh + ib + (size_t)(i0 + r)*64 + ch*8);
    }
    __syncthreads();   // Q visible to all warps

    const int rr  = (lane & 7) + ((lane >> 3) & 1) * 8;
    const int csl = lane >> 4;

    unsigned qh[4][4];
    #pragma unroll
    for(int ks = 0; ks < 4; ks++)
        ldsm4(qh[ks], sb + SWZ((w*16 + rr)*128 + (ks*2 + csl)*16));

    float o_[8][4];
    #pragma unroll
    for(int a=0;a<8;a++)
        #pragma unroll
        for(int e=0;e<4;e++) o_[a][e]=0.0f;
    float l0 = 0.0f, l1 = 0.0f;

    for(int ci = 0; ci < nch; ci++){
        const int j0 = (kt0 + ci) * 64;
        if(ci + 1 < nch) CP_WAIT1();
        else             CP_WAIT0();
        __syncthreads();                       // data of stage ci visible; stage ci+2 free
        if(ci + 2 < nch) A_ISSUE(kt0 + ci + 2, (ci + 2) % 3);
        const unsigned base = sb + 16384 + (ci % 3) * 16384;

        // S = Q @ K^T  (pure fp16)
        float s_[8][4];
        #pragma unroll
        for(int a=0;a<8;a++)
            #pragma unroll
            for(int e=0;e<4;e++) s_[a][e]=0.0f;
        #pragma unroll
        for(int ks = 0; ks < 4; ks++){
            unsigned kbh[4][4];
            #pragma unroll
            for(int g = 0; g < 4; g++)
                ldsm4(kbh[g], base + SWZ((g*16 + rr)*128 + (ks*2 + csl)*16));
            #pragma unroll
            for(int g = 0; g < 4; g++)
                #pragma unroll
                for(int sub = 0; sub < 2; sub++)
                    mma16816(s_[g*2 + sub], qh[ks], kbh[g][sub], kbh[g][sub+2]);
        }

        // exp2 with analytic shift; build P fragments (fp16)
        unsigned ph[4][4];
        #pragma unroll
        for(int nt = 0; nt < 8; nt++){
            const float jb = (float)(j0 + nt*8 + (lane & 3)*2 - 2047);
            float p0 = ex2f(fmaf(c2, jb,        s_[nt][0]));
            float p1 = ex2f(fmaf(c2, jb + 1.0f, s_[nt][1]));
            float p2 = ex2f(fmaf(c2, jb,        s_[nt][2]));
            float p3 = ex2f(fmaf(c2, jb + 1.0f, s_[nt][3]));
            l0 += p0 + p1;
            l1 += p2 + p3;
            const int kk = nt >> 1, od = nt & 1;
            ph[kk][od ? 2 : 0] = packh(p0, p1);
            ph[kk][od ? 3 : 1] = packh(p2, p3);
        }

        // O += P @ V  (V stored [s][d]; B-fragments via ldmatrix.trans; fp16)
        #pragma unroll
        for(int kk = 0; kk < 4; kk++){
            unsigned vbh[4][4];
            #pragma unroll
            for(int g = 0; g < 4; g++)
                ldsm4t(vbh[g], base + 8192 + SWZ((kk*16 + rr)*128 + (g*2 + csl)*16));
            #pragma unroll
            for(int g = 0; g < 4; g++)
                #pragma unroll
                for(int sub = 0; sub < 2; sub++)
                    mma16816(o_[g*2 + sub], ph[kk], vbh[g][2*sub], vbh[g][2*sub+1]);
        }
    }

    // reduce l within quads
    l0 += __shfl_xor_sync(0xffffffffu, l0, 1);
    l0 += __shfl_xor_sync(0xffffffffu, l0, 2);
    l1 += __shfl_xor_sync(0xffffffffu, l1, 1);
    l1 += __shfl_xor_sync(0xffffffffu, l1, 2);
    const float inv0 = 1.0f / l0, inv1 = 1.0f / l1;

    const int r0g = i0 + w*16 + (lane >> 2);
    float* op0 = out + ((size_t)b*2048 + r0g)*1024 + h*64 + (lane & 3)*2;
    float* op1 = out + ((size_t)b*2048 + r0g + 8)*1024 + h*64 + (lane & 3)*2;
    #pragma unroll
    for(int nt = 0; nt < 8; nt++){
        *(float2*)(op0 + nt*8) = make_float2(o_[nt][0]*inv0, o_[nt][1]*inv0);
        *(float2*)(op1 + nt*8) = make_float2(o_[nt][2]*inv1, o_[nt][3]*inv1);
    }
}

// ------------------------------- launch --------------------------------------
extern "C" void kernel_launch(void* const* d_in, const int* in_sizes, int n_in,
                              void* d_out, int out_size)
{
    const float* x = (const float*)d_in[0];
    const float* w = (const float*)d_in[1];
    float* out = (float*)d_out;
    (void)in_sizes; (void)n_in; (void)out_size;

    splitx_kernel<<<4096, 256>>>(x);
    splitw_kernel<<<dim3(48, 16), 256>>>(w);

    cudaFuncSetAttribute(gemm_kernel, cudaFuncAttributeMaxDynamicSharedMemorySize, GSM);
    gemm_kernel<<<dim3(24, 64), 256, GSM>>>();

    cudaFuncSetAttribute(attn_kernel, cudaFuncAttributeMaxDynamicSharedMemorySize, ASM);
    attn_kernel<<<dim3(16, 64), 256, ASM>>>(out);
}

// round 17
// speedup vs baseline: 2.6073x; 1.0340x over previous
#include <cuda_runtime.h>
#include <cuda_fp16.h>
#include <math.h>

#define QF_ 0.04508422002777998f   // log2(e)/32

// ------------------------- device scratch (no allocs) ----------------------
__device__ __half g_Xh[(size_t)8192*1024];
__device__ __half g_Wh[(size_t)3072*1024];   // W^T [n][k]
__device__ __half g_Qh[(size_t)64*2048*64];  // [bh][s][d] (pre-scaled by QF)
__device__ __half g_Kh[(size_t)64*2048*64];
__device__ __half g_Vsh[(size_t)64*2048*64]; // [bh][s][d]

// ------------------------------ helpers ------------------------------------
__device__ __forceinline__ unsigned su32(const void* p){
    unsigned a;
    asm("{ .reg .u64 t; cvta.to.shared.u64 t, %1; cvt.u32.u64 %0, t; }":"=r"(a):"l"(p));
    return a;
}
#define SWZ(o) ((unsigned)(o) ^ ((((unsigned)(o)) >> 3) & 0x70))

__device__ __forceinline__ void cpa16(unsigned dst, const void* src){
    asm volatile("cp.async.cg.shared.global [%0], [%1], 16;"::"r"(dst),"l"(src));
}
#define CP_COMMIT() asm volatile("cp.async.commit_group;" ::: "memory")
#define CP_WAIT1()  asm volatile("cp.async.wait_group 1;" ::: "memory")
#define CP_WAIT0()  asm volatile("cp.async.wait_group 0;" ::: "memory")

__device__ __forceinline__ void ldsm4(unsigned* r, unsigned a){
    asm volatile("ldmatrix.sync.aligned.m8n8.x4.shared.b16 {%0,%1,%2,%3}, [%4];"
                 : "=r"(r[0]),"=r"(r[1]),"=r"(r[2]),"=r"(r[3]) : "r"(a));
}
__device__ __forceinline__ void ldsm4t(unsigned* r, unsigned a){
    asm volatile("ldmatrix.sync.aligned.m8n8.x4.trans.shared.b16 {%0,%1,%2,%3}, [%4];"
                 : "=r"(r[0]),"=r"(r[1]),"=r"(r[2]),"=r"(r[3]) : "r"(a));
}
__device__ __forceinline__ void mma16816(float* d, const unsigned* a, unsigned b0, unsigned b1){
    asm volatile("mma.sync.aligned.m16n8k16.row.col.f32.f16.f16.f32 "
                 "{%0,%1,%2,%3},{%4,%5,%6,%7},{%8,%9},{%0,%1,%2,%3};"
                 : "+f"(d[0]),"+f"(d[1]),"+f"(d[2]),"+f"(d[3])
                 : "r"(a[0]),"r"(a[1]),"r"(a[2]),"r"(a[3]),"r"(b0),"r"(b1));
}
__device__ __forceinline__ float ex2f(float x){
    float r; asm("ex2.approx.ftz.f32 %0, %1;":"=f"(r):"f"(x)); return r;
}
__device__ __forceinline__ unsigned packh(float a, float b){
    __half2 h = __floats2half2_rn(a, b);
    return *(unsigned*)&h;
}

// -------------------- fused split X + transpose W ----------------------------
// blocks [0, 4096): X hi-split (8 floats/thread).
// blocks [4096, 4864): W transpose+convert, 64x64 tile each.
__global__ __launch_bounds__(256) void split_kernel(const float* __restrict__ x,
                                                    const float* __restrict__ w){
    if(blockIdx.x < 4096){
        size_t i = ((size_t)blockIdx.x * 256 + threadIdx.x) * 8;
        float4 a = *(const float4*)(x + i);
        float4 b = *(const float4*)(x + i + 4);
        uint4 H;
        H.x = packh(a.x, a.y); H.y = packh(a.z, a.w);
        H.z = packh(b.x, b.y); H.w = packh(b.z, b.w);
        *(uint4*)(g_Xh + i) = H;
        return;
    }
    __shared__ float ws[64][65];
    const int blk = blockIdx.x - 4096;          // 0..767 = 48 x 16
    const int n0 = (blk % 48) * 64, k0 = (blk / 48) * 64;
    #pragma unroll
    for(int i=0;i<4;i++){
        int e = i*256 + threadIdx.x;
        int r = e >> 4, c4 = (e & 15) * 4;
        float4 t = *(const float4*)(w + (size_t)(k0 + r) * 3072 + n0 + c4);
        ws[r][c4+0]=t.x; ws[r][c4+1]=t.y; ws[r][c4+2]=t.z; ws[r][c4+3]=t.w;
    }
    __syncthreads();
    int n = threadIdx.x >> 2, sg = (threadIdx.x & 3) * 16;
    unsigned H[8];
    #pragma unroll
    for(int j=0;j<8;j++)
        H[j] = packh(ws[sg + 2*j][n], ws[sg + 2*j + 1][n]);
    __half* dh = g_Wh + (size_t)(n0 + n) * 1024 + k0 + sg;
    *(uint4*)(dh)     = *(uint4*)(H);
    *(uint4*)(dh + 8) = *(uint4*)(H + 4);
}

// ------------------------------ QKV GEMM ------------------------------------
// grid (24, 64), 256 thr, CTA 128x128, warp tile 32x64 (proven shape).
// Double-buffered cp.async. Stage s (32768 B each): AH +0 (16K), BH +16K.
// Epilogue staging 34816 B reuses stage area. GSM=65536 (2 CTAs/SM).
#define GSM 65536

__global__ __launch_bounds__(256) void gemm_kernel(){
    extern __shared__ char sm[];
    const unsigned sb = su32(sm);
    const int tid = threadIdx.x, lane = tid & 31, wid = tid >> 5;
    const int wr = wid & 3, wc = wid >> 2;
    const int m0 = blockIdx.y * 128, n0 = blockIdx.x * 128;

    float acc[2][8][4];
    #pragma unroll
    for(int a=0;a<2;a++)
        #pragma unroll
        for(int b=0;b<8;b++)
            #pragma unroll
            for(int c=0;c<4;c++) acc[a][b][c]=0.0f;

    const int rr  = (lane & 7) + ((lane >> 3) & 1) * 8;
    const int csl = lane >> 4;

    const int lr = tid >> 3, lch = tid & 7;
    const unsigned lo_sw[4] = { SWZ((lr     )*128 + lch*16), SWZ((lr + 32)*128 + lch*16),
                                SWZ((lr + 64)*128 + lch*16), SWZ((lr + 96)*128 + lch*16) };

    #define G_ISSUE(c, st) do{ \
        const int k0_ = (c) * 64; \
        const unsigned base_ = sb + (st) * 32768; \
        _Pragma("unroll") \
        for(int j_ = 0; j_ < 4; j_++){ \
            int r_ = lr + j_*32; \
            unsigned o_ = lo_sw[j_]; \
            cpa16(base_ + o_,         g_Xh + (size_t)(m0 + r_) * 1024 + k0_ + lch*8); \
            cpa16(base_ + 16384 + o_, g_Wh + (size_t)(n0 + r_) * 1024 + k0_ + lch*8); \
        } \
        CP_COMMIT(); \
    }while(0)

    G_ISSUE(0, 0);

    for(int c = 0; c < 16; c++){
        if(c < 15){ G_ISSUE(c + 1, (c + 1) & 1); CP_WAIT1(); }
        else      { CP_WAIT0(); }
        __syncthreads();
        const unsigned base = sb + (c & 1) * 32768;

        #pragma unroll
        for(int ks = 0; ks < 4; ks++){
            unsigned ah[2][4];
            const int cc2 = ks*2 + csl;
            #pragma unroll
            for(int mt = 0; mt < 2; mt++)
                ldsm4(ah[mt], base + SWZ((wr*32 + mt*16 + rr)*128 + cc2*16));
            #pragma unroll
            for(int hf = 0; hf < 2; hf++){
                unsigned bh[2][4];
                #pragma unroll
                for(int g = 0; g < 2; g++)
                    ldsm4(bh[g], base + 16384 + SWZ((wc*64 + hf*32 + g*16 + rr)*128 + cc2*16));
                #pragma unroll
                for(int g = 0; g < 2; g++)
                    #pragma unroll
                    for(int sub = 0; sub < 2; sub++){
                        const int nt = hf*4 + g*2 + sub;
                        #pragma unroll
                        for(int mt = 0; mt < 2; mt++)
                            mma16816(acc[mt][nt], ah[mt], bh[g][sub], bh[g][sub+2]);
                    }
            }
        }
        __syncthreads();
    }

    const int part = n0 >> 10;          // 0=K, 1=Q, 2=V
    const int h0   = (n0 & 1023) >> 6;
    const float sc = (part == 1) ? QF_ : 1.0f;
    __half* gh = (part == 0) ? g_Kh : (part == 1) ? g_Qh : g_Vsh;

    #pragma unroll
    for(int mt = 0; mt < 2; mt++)
        #pragma unroll
        for(int nt = 0; nt < 8; nt++){
            const int r0 = wr*32 + mt*16 + (lane >> 2);
            const int cc = wc*64 + nt*8 + (lane & 3)*2;
            *(unsigned*)(sm + r0*272 + cc*2)     = packh(acc[mt][nt][0]*sc, acc[mt][nt][1]*sc);
            *(unsigned*)(sm + (r0+8)*272 + cc*2) = packh(acc[mt][nt][2]*sc, acc[mt][nt][3]*sc);
        }
    __syncthreads();

    #pragma unroll
    for(int j = 0; j < 8; j++){
        int i = tid + j*256;
        int r = i >> 4, cc = i & 15;
        int gr = m0 + r;
        int b = gr >> 11, s = gr & 2047;
        int h = h0 + (cc >> 3);
        size_t off = (((size_t)(b*16 + h)*2048 + s)*64) + (size_t)(cc & 7)*8;
        *(uint4*)(gh + off) = *(uint4*)(sm + r*272 + cc*16);
    }
}

// ------------------------------ attention -----------------------------------
// grid (16, 64): (qtile, bh'). Heavy heads first: h = 15 - (bh'&15).
// 256 thr (8 warps, 16 q-rows each). Pure fp16. 2-stage cp.async (R15-proven).
// smem: QH @0 (16K). Stage s (16384 B each) @16384: KH +0, VH +8K.
// ASM = 16384 + 32768 = 49152.
#define ASM 49152

__global__ __launch_bounds__(256,2) void attn_kernel(float* __restrict__ out){
    extern __shared__ char sm[];
    const unsigned sb = su32(sm);
    const int tid = threadIdx.x, lane = tid & 31, w = tid >> 5;
    const int qt = blockIdx.x;
    const int h = 15 - ((int)blockIdx.y & 15);   // heavy heads first
    const int b = (int)blockIdx.y >> 4;
    const int bh = b * 16 + h;
    const int i0 = qt * 128;
    const size_t ib = (size_t)bh * 131072;

    const float slope = exp2f(-0.5f * (float)(h + 1));
    const float c2 = slope * 1.4426950408889634f;

    // load Q tile (plain stores, swizzled)
    #pragma unroll
    for(int j = 0; j < 4; j++){
        int i = tid + j*256;
        int r = i >> 3, ch = i & 7;
        unsigned o = SWZ(r*128 + ch*16);
        *(uint4*)(sm + o) = *(const uint4*)(g_Qh + ib + (size_t)(i0 + r)*64 + ch*8);
    }

    int kt0 = 0;
    while(kt0 < 31 && c2 * (float)(1984 - 64*kt0) > 17.0f) kt0++;
    const int nch = 32 - kt0;

    const int lr = tid >> 3, lch = tid & 7;     // lr 0..31
    #define A_ISSUE(kt, st) do{ \
        const int j0_ = (kt) * 64; \
        const unsigned base_ = sb + 16384 + (st) * 16384; \
        _Pragma("unroll") \
        for(int j_ = 0; j_ < 2; j_++){ \
            int r_ = lr + j_*32; \
            unsigned o_ = SWZ(r_*128 + lch*16); \
            size_t gx_ = ib + (size_t)(j0_ + r_)*64 + lch*8; \
            cpa16(base_ + o_,        g_Kh  + gx_); \
            cpa16(base_ + 8192 + o_, g_Vsh + gx_); \
        } \
        CP_COMMIT(); \
    }while(0)

    A_ISSUE(kt0, 0);
    __syncthreads();   // Q visible

    const int rr  = (lane & 7) + ((lane >> 3) & 1) * 8;
    const int csl = lane >> 4;

    unsigned qh[4][4];
    #pragma unroll
    for(int ks = 0; ks < 4; ks++)
        ldsm4(qh[ks], sb + SWZ((w*16 + rr)*128 + (ks*2 + csl)*16));

    float o_[8][4];
    #pragma unroll
    for(int a=0;a<8;a++)
        #pragma unroll
        for(int e=0;e<4;e++) o_[a][e]=0.0f;
    float l0 = 0.0f, l1 = 0.0f;

    for(int ci = 0; ci < nch; ci++){
        const int kt = kt0 + ci;
        const int j0 = kt * 64;
        if(ci + 1 < nch){ A_ISSUE(kt + 1, (ci + 1) & 1); CP_WAIT1(); }
        else            { CP_WAIT0(); }
        __syncthreads();
        const unsigned base = sb + 16384 + (ci & 1) * 16384;

        // S = Q @ K^T  (pure fp16)
        float s_[8][4];
        #pragma unroll
        for(int a=0;a<8;a++)
            #pragma unroll
            for(int e=0;e<4;e++) s_[a][e]=0.0f;
        #pragma unroll
        for(int ks = 0; ks < 4; ks++){
            unsigned kbh[4][4];
            #pragma unroll
            for(int g = 0; g < 4; g++)
                ldsm4(kbh[g], base + SWZ((g*16 + rr)*128 + (ks*2 + csl)*16));
            #pragma unroll
            for(int g = 0; g < 4; g++)
                #pragma unroll
                for(int sub = 0; sub < 2; sub++)
                    mma16816(s_[g*2 + sub], qh[ks], kbh[g][sub], kbh[g][sub+2]);
        }

        // exp2 with analytic shift; build P fragments (fp16)
        unsigned ph[4][4];
        #pragma unroll
        for(int nt = 0; nt < 8; nt++){
            const float jb = (float)(j0 + nt*8 + (lane & 3)*2 - 2047);
            float p0 = ex2f(fmaf(c2, jb,        s_[nt][0]));
            float p1 = ex2f(fmaf(c2, jb + 1.0f, s_[nt][1]));
            float p2 = ex2f(fmaf(c2, jb,        s_[nt][2]));
            float p3 = ex2f(fmaf(c2, jb + 1.0f, s_[nt][3]));
            l0 += p0 + p1;
            l1 += p2 + p3;
            const int kk = nt >> 1, od = nt & 1;
            ph[kk][od ? 2 : 0] = packh(p0, p1);
            ph[kk][od ? 3 : 1] = packh(p2, p3);
        }

        // O += P @ V  (V stored [s][d]; B-fragments via ldmatrix.trans; fp16)
        #pragma unroll
        for(int kk = 0; kk < 4; kk++){
            unsigned vbh[4][4];
            #pragma unroll
            for(int g = 0; g < 4; g++)
                ldsm4t(vbh[g], base + 8192 + SWZ((kk*16 + rr)*128 + (g*2 + csl)*16));
            #pragma unroll
            for(int g = 0; g < 4; g++)
                #pragma unroll
                for(int sub = 0; sub < 2; sub++)
                    mma16816(o_[g*2 + sub], ph[kk], vbh[g][2*sub], vbh[g][2*sub+1]);
        }
        __syncthreads();
    }

    // reduce l within quads
    l0 += __shfl_xor_sync(0xffffffffu, l0, 1);
    l0 += __shfl_xor_sync(0xffffffffu, l0, 2);
    l1 += __shfl_xor_sync(0xffffffffu, l1, 1);
    l1 += __shfl_xor_sync(0xffffffffu, l1, 2);
    const float inv0 = 1.0f / l0, inv1 = 1.0f / l1;

    const int r0g = i0 + w*16 + (lane >> 2);
    float* op0 = out + ((size_t)b*2048 + r0g)*1024 + h*64 + (lane & 3)*2;
    float* op1 = out + ((size_t)b*2048 + r0g + 8)*1024 + h*64 + (lane & 3)*2;
    #pragma unroll
    for(int nt = 0; nt < 8; nt++){
        *(float2*)(op0 + nt*8) = make_float2(o_[nt][0]*inv0, o_[nt][1]*inv0);
        *(float2*)(op1 + nt*8) = make_float2(o_[nt][2]*inv1, o_[nt][3]*inv1);
    }
}

// ------------------------------- launch --------------------------------------
extern "C" void kernel_launch(void* const* d_in, const int* in_sizes, int n_in,
                              void* d_out, int out_size)
{
    const float* x = (const float*)d_in[0];
    const float* w = (const float*)d_in[1];
    float* out = (float*)d_out;
    (void)in_sizes; (void)n_in; (void)out_size;

    split_kernel<<<4864, 256>>>(x, w);

    cudaFuncSetAttribute(gemm_kernel, cudaFuncAttributeMaxDynamicSharedMemorySize, GSM);
    gemm_kernel<<<dim3(24, 64), 256, GSM>>>();

    cudaFuncSetAttribute(attn_kernel, cudaFuncAttributeMaxDynamicSharedMemorySize, ASM);
    attn_kernel<<<dim3(16, 64), 256, ASM>>>(out);
}